// round 14
// baseline (speedup 1.0000x reference)
#include <cuda_runtime.h>
#include <math.h>

// Problem constants (fixed by reference setup_inputs)
#define BB 4
#define HH 8
#define SS 2048
#define DD 8
#define CAP 32
#define RPB 8                     // rows per block
#define NT  512                   // threads per block
#define NB ((BB*SS)/RPB)          // 1024 blocks
#define M0 0.015f                 // speculative margin; verified by the tail block

// Scratch. g_xn2: monotone max over fixed inputs (same value every call).
// g_ticket: monotone; (ticket % NB)==NB-1 selects the last block each replay
// (NB divides 2^32, so unsigned wrap is harmless). g_nover reset by tail.
__device__ unsigned g_xn2;
__device__ unsigned g_ticket;
__device__ int      g_nover;
__device__ int      g_olist[BB*SS];

// ---------------------------------------------------------------------------
// Handler for rows with 2 <= cnt <= CAP. Called by threads 0..255 only
// (warp w = head w, lane i = candidate i); warp-local shuffles, no bar.
// Exact softmax over the candidate set (excluded keys carry < e^-30
// relative weight; margin verified by the tail).
// ---------------------------------------------------------------------------
__device__ __noinline__ void rare_block(
        const float* __restrict__ x,
        const float* __restrict__ Wq, const float* __restrict__ bq,
        const float* __restrict__ Wk, const float* __restrict__ bk,
        float* __restrict__ out,
        int b, int q, int cnt, const int* s_idx, const float* s_mv) {
    int t    = threadIdx.x;
    int w    = t >> 5;          // 0..7 (caller guarantees t < 256)
    int lane = t & 31;
    int bh   = b * HH + w;
    const float* xb = x + (size_t)bh * SS * DD;

    const float4* xq = (const float4*)(xb + (size_t)q * DD);
    float4 a0 = xq[0], a1 = xq[1];
    float xv[8] = {a0.x, a0.y, a0.z, a0.w, a1.x, a1.y, a1.z, a1.w};
    float qv[8];
#pragma unroll
    for (int i = 0; i < 8; i++) {
        float s = __ldg(bq + i);
#pragma unroll
        for (int j = 0; j < 8; j++) s += xv[j] * __ldg(Wq + i*8 + j);
        qv[i] = s;
    }

    float score = -INFINITY;
    float xk[8] = {0,0,0,0,0,0,0,0};
    if (lane < cnt) {
        int kk = s_idx[lane];
        const float4* xr = (const float4*)(xb + (size_t)kk * DD);
        float4 c0 = xr[0], c1 = xr[1];
        xk[0]=c0.x; xk[1]=c0.y; xk[2]=c0.z; xk[3]=c0.w;
        xk[4]=c1.x; xk[5]=c1.y; xk[6]=c1.z; xk[7]=c1.w;
        float sdot = 0.f;
#pragma unroll
        for (int i = 0; i < 8; i++) {
            float kv = __ldg(bk + i);
#pragma unroll
            for (int j = 0; j < 8; j++) kv += xk[j] * __ldg(Wk + i*8 + j);
            sdot += qv[i] * kv;
        }
        score = sdot * 0.35355339059f - 10000.0f * s_mv[lane];
    }

    float m = score;
#pragma unroll
    for (int o = 16; o; o >>= 1) m = fmaxf(m, __shfl_xor_sync(0xffffffffu, m, o));
    float p = (lane < cnt) ? expf(score - m) : 0.f;
    float l = p;
#pragma unroll
    for (int o = 16; o; o >>= 1) l += __shfl_xor_sync(0xffffffffu, l, o);
    float acc[8];
#pragma unroll
    for (int i = 0; i < 8; i++) {
        float s = p * xk[i];
#pragma unroll
        for (int o = 16; o; o >>= 1) s += __shfl_xor_sync(0xffffffffu, s, o);
        acc[i] = s;
    }
    if (lane == 0) {
        float inv = 1.0f / l;
        float4* o = (float4*)(out + ((size_t)bh * SS + q) * DD);
        o[0] = make_float4(acc[0]*inv, acc[1]*inv, acc[2]*inv, acc[3]*inv);
        o[1] = make_float4(acc[4]*inv, acc[5]*inv, acc[6]*inv, acc[7]*inv);
    }
}

// ---------------------------------------------------------------------------
// Exact full-row attention for one (row, head), one warp. Tail-only.
// ---------------------------------------------------------------------------
__device__ __noinline__ void full_row(
        const float* __restrict__ x, const float* __restrict__ mask,
        const float* __restrict__ Wq, const float* __restrict__ bq,
        const float* __restrict__ Wk, const float* __restrict__ bk,
        float* __restrict__ out, int row, int h, int lane) {
    int b  = row >> 11;
    int q  = row & (SS - 1);
    int bh = b * HH + h;
    const float* xb = x + (size_t)bh * SS * DD;

    const float4* xq = (const float4*)(xb + (size_t)q * DD);
    float4 a0 = xq[0], a1 = xq[1];
    float xv[8] = {a0.x, a0.y, a0.z, a0.w, a1.x, a1.y, a1.z, a1.w};
    float qv[8];
#pragma unroll
    for (int i = 0; i < 8; i++) {
        float s = __ldg(bq + i);
#pragma unroll
        for (int j = 0; j < 8; j++) s += xv[j] * __ldg(Wq + i*8 + j);
        qv[i] = s;
    }

    const float* mrow = mask + (size_t)(b * SS + q) * SS;
    float m = -INFINITY, l = 0.f;
    float acc[8] = {0,0,0,0,0,0,0,0};
#pragma unroll 1
    for (int kk = lane; kk < SS; kk += 32) {
        const float4* xr = (const float4*)(xb + (size_t)kk * DD);
        float4 c0 = xr[0], c1 = xr[1];
        float xk[8] = {c0.x,c0.y,c0.z,c0.w,c1.x,c1.y,c1.z,c1.w};
        float sdot = 0.f;
#pragma unroll
        for (int i = 0; i < 8; i++) {
            float kv = __ldg(bk + i);
#pragma unroll
            for (int j = 0; j < 8; j++) kv += xk[j] * __ldg(Wk + i*8 + j);
            sdot += qv[i] * kv;
        }
        float sc = sdot * 0.35355339059f - 10000.0f * mrow[kk];
        float nm = fmaxf(m, sc);
        float corr = expf(m - nm);
        float p = expf(sc - nm);
        l = l * corr + p;
#pragma unroll
        for (int i = 0; i < 8; i++) acc[i] = acc[i]*corr + p*xk[i];
        m = nm;
    }
#pragma unroll
    for (int o = 16; o; o >>= 1) {
        float om = __shfl_xor_sync(0xffffffffu, m, o);
        float ol = __shfl_xor_sync(0xffffffffu, l, o);
        float oa[8];
#pragma unroll
        for (int i = 0; i < 8; i++) oa[i] = __shfl_xor_sync(0xffffffffu, acc[i], o);
        float nm = fmaxf(m, om);
        float c1 = expf(m - nm), c2 = expf(om - nm);
        l = l * c1 + ol * c2;
#pragma unroll
        for (int i = 0; i < 8; i++) acc[i] = acc[i]*c1 + oa[i]*c2;
        m = nm;
    }
    if (lane == 0) {
        float inv = 1.0f / l;
        float4* o = (float4*)(out + ((size_t)bh * SS + q) * DD);
        o[0] = make_float4(acc[0]*inv, acc[1]*inv, acc[2]*inv, acc[3]*inv);
        o[1] = make_float4(acc[4]*inv, acc[5]*inv, acc[6]*inv, acc[7]*inv);
    }
}

// ---------------------------------------------------------------------------
// Tail (one block per call, all NT threads): verifies
// M* = (2*qb+30)*1e-4 <= M0 with qb = (|Wq|_F xm+|bq|)(|Wk|_F xm+|bk|)/sqrt(8),
// xm = sqrt(g_xn2) (every excluded key then carries < e^-30 relative weight),
// processes overflow rows exactly; if verification failed (never for this
// data), recomputes ALL rows exactly. Resets g_nover for the next replay.
// ---------------------------------------------------------------------------
__device__ __noinline__ void tail_block(
        const float* __restrict__ x, const float* __restrict__ mask,
        const float* __restrict__ Wq, const float* __restrict__ bq,
        const float* __restrict__ Wk, const float* __restrict__ bk,
        float* __restrict__ out) {
    int t    = threadIdx.x;
    int lane = t & 31;
    int w    = t >> 5;            // 0..15

    float wq2 = 0.f, wk2 = 0.f, b2q = 0.f, b2k = 0.f;
    if (t < 64) { float a = __ldg(Wq + t), c = __ldg(Wk + t); wq2 = a*a; wk2 = c*c; }
    if (t < 8)  { float a = __ldg(bq + t), c = __ldg(bk + t); b2q = a*a; b2k = c*c; }
#pragma unroll
    for (int o = 16; o; o >>= 1) {
        wq2 += __shfl_xor_sync(0xffffffffu, wq2, o);
        wk2 += __shfl_xor_sync(0xffffffffu, wk2, o);
        b2q += __shfl_xor_sync(0xffffffffu, b2q, o);
        b2k += __shfl_xor_sync(0xffffffffu, b2k, o);
    }
    __shared__ float s_part[8];
    __shared__ int   s_fb;
    if (lane == 0 && w < 2) {
        s_part[w*4 + 0] = wq2; s_part[w*4 + 1] = wk2;
        s_part[w*4 + 2] = b2q; s_part[w*4 + 3] = b2k;
    }
    __syncthreads();
    if (t == 0) {
        float fq  = s_part[0] + s_part[4], fk  = s_part[1] + s_part[5];
        float nbq = s_part[2] + s_part[6], nbk = s_part[3] + s_part[7];
        float xm = sqrtf(__uint_as_float(g_xn2));
        float qb = (sqrtf(fq)*xm + sqrtf(nbq)) * (sqrtf(fk)*xm + sqrtf(nbk)) * 0.35355339059f;
        float mstar = (2.0f * qb + 30.0f) * 1e-4f;
        s_fb = (mstar > M0) ? 1 : 0;
    }
    __syncthreads();

    int fb    = s_fb;
    int ntask = (fb ? (BB*SS) : g_nover) * HH;   // warp tasks (normally 0)
    for (int task = w; task < ntask; task += NT/32) {
        int r = fb ? (task >> 3) : g_olist[task >> 3];
        full_row(x, mask, Wq, bq, Wk, bk, out, r, task & 7, lane);
    }
    __syncthreads();
    if (t == 0) g_nover = 0;                     // reset for next replay
}

// ---------------------------------------------------------------------------
// Single kernel: 512-thread block per 8 consecutive (b,q) rows.
// Each thread front-loads 8 independent float4s (one per row) -> MLP=8.
// Skip-scan: a thread's 4-value row-min filters the detailed candidate scan
// (~99.8% of threads do 1 compare per row instead of 4 + atomics).
// cnt==1 (~95% of rows): softmax weight exactly 1 -> copy x row for 8 heads.
// 2<=cnt<=CAP: in-block handler. cnt>CAP: overflow list for the tail.
// ---------------------------------------------------------------------------
__global__ void __launch_bounds__(NT, 2) k_all(
        const float* __restrict__ x, const float* __restrict__ mask,
        const float* __restrict__ Wq, const float* __restrict__ bq,
        const float* __restrict__ Wk, const float* __restrict__ bk,
        float* __restrict__ out) {
    int row0 = blockIdx.x * RPB;
    int b    = row0 >> 11;              // 8 consecutive rows share b (2048 % 8 == 0)
    int t    = threadIdx.x;
    int w    = t >> 5;                  // 0..15
    int lane = t & 31;

    __shared__ float warpmin[RPB][16];
    __shared__ float s_thresh[RPB];
    __shared__ int   s_cnt[RPB];
    __shared__ int   s_idx[RPB][CAP];
    __shared__ float s_mv[RPB][CAP];
    __shared__ int   s_last;

    // front-load: one float4 of each of the 8 rows (independent, 8 in flight)
    const float4* mr = (const float4*)(mask + (size_t)row0 * SS) + t;
    float4 va[RPB];
#pragma unroll
    for (int r = 0; r < RPB; r++) va[r] = mr[r * (SS/4)];

    // x-norm side-task: 128 threads, one float4 each (1024 blocks x 128 = all of x)
    float xn = 0.f;
    if (t < 128) {
        float4 a = ((const float4*)x)[(size_t)blockIdx.x * 128 + t];
        xn = a.x*a.x + a.y*a.y + a.z*a.z + a.w*a.w;
    }
#pragma unroll
    for (int o = 16; o; o >>= 1) xn = fmaxf(xn, __shfl_xor_sync(0xffffffffu, xn, o));
    if (lane == 0 && w < 4) atomicMax(&g_xn2, __float_as_uint(xn));  // >=0: uint==float order

    // stage 1: per-warp min per row
#pragma unroll
    for (int r = 0; r < RPB; r++) {
        float mn = fminf(fminf(va[r].x, va[r].y), fminf(va[r].z, va[r].w));
#pragma unroll
        for (int o = 16; o; o >>= 1) mn = fminf(mn, __shfl_xor_sync(0xffffffffu, mn, o));
        if (lane == 0) warpmin[r][w] = mn;
    }
    __syncthreads();

    // stage 2: warp r reduces row r's 16 partials
    if (t < 256) {
        int r = w;                       // warps 0..7 handle rows 0..7
        float mn = (lane < 16) ? warpmin[r][lane] : __int_as_float(0x7f800000);
#pragma unroll
        for (int o = 8; o; o >>= 1) mn = fminf(mn, __shfl_xor_sync(0xffffffffu, mn, o));
        if (lane == 0) { s_thresh[r] = mn + M0; s_cnt[r] = 0; }
    }
    __syncthreads();

    // skip-scan: detailed scan only if this thread's 4-value min passes
#pragma unroll
    for (int r = 0; r < RPB; r++) {
        float th = s_thresh[r];
        float tmn = fminf(fminf(va[r].x, va[r].y), fminf(va[r].z, va[r].w));
        if (tmn <= th) {
            float vv[4] = {va[r].x, va[r].y, va[r].z, va[r].w};
#pragma unroll
            for (int j = 0; j < 4; j++) {
                if (vv[j] <= th) {
                    int p = atomicAdd(&s_cnt[r], 1);
                    if (p < CAP) { s_idx[r][p] = t * 4 + j; s_mv[r][p] = vv[j]; }
                }
            }
        }
    }
    __syncthreads();

    // cnt==1 rows: all 8 resolved in parallel (128 threads; 16 per row)
    if (t < 16 * RPB) {
        int r = t >> 4, sub = t & 15;
        if (s_cnt[r] == 1) {
            int h = sub >> 1, p = sub & 1;
            int kk = s_idx[r][0];
            int q  = (row0 + r) & (SS - 1);
            size_t base = ((size_t)(b * HH + h) * SS);
            const float4* src = (const float4*)(x   + (base + kk) * DD);
            float4*       dst = (float4*)      (out + (base + q ) * DD);
            dst[p] = src[p];
        }
    }

    // rare rows: block-uniform branches, handled sequentially
#pragma unroll 1
    for (int r = 0; r < RPB; r++) {
        int cnt = s_cnt[r];
        if (cnt >= 2 && cnt <= CAP) {
            if (t < 256)
                rare_block(x, Wq, bq, Wk, bk, out,
                           b, (row0 + r) & (SS - 1), cnt, s_idx[r], s_mv[r]);
        } else if (cnt > CAP) {
            if (t == 0) g_olist[atomicAdd(&g_nover, 1)] = row0 + r;
        }
    }

    // ---- tail election: monotone ticket (no reset needed, NB | 2^32) ----
    __syncthreads();
    if (t == 0) {
        __threadfence();
        unsigned tk = atomicAdd(&g_ticket, 1u);
        s_last = ((tk & (NB - 1u)) == NB - 1u) ? 1 : 0;
    }
    __syncthreads();
    if (!s_last) return;
    __threadfence();

    tail_block(x, mask, Wq, bq, Wk, bk, out);
}

extern "C" void kernel_launch(void* const* d_in, const int* in_sizes, int n_in,
                              void* d_out, int out_size) {
    const float* x    = (const float*)d_in[0];  // [4,8,2048,8]
    const float* mask = (const float*)d_in[1];  // [4,1,2048,2048]
    const float* Wq   = (const float*)d_in[2];  // [8,8]
    const float* bq   = (const float*)d_in[3];  // [8]
    const float* Wk   = (const float*)d_in[4];  // [8,8]
    const float* bk   = (const float*)d_in[5];  // [8]
    float* out = (float*)d_out;                 // [4,8,2048,8]

    k_all<<<NB, NT>>>(x, mask, Wq, bq, Wk, bk, out);
}